// round 7
// baseline (speedup 1.0000x reference)
#include <cuda_runtime.h>

#define NE 2049   // E is NE x NE
#define NH 2048   // Hx cols / Hy rows
#define NW 2047   // Hx rows / Hy cols
#define CFLf 0.35f

#define KF0 (-11.0f/6.0f)
#define KF1 (3.0f)
#define KF2 (-1.5f)
#define KF3 (1.0f/3.0f)
#define KB0 (-1.0f/3.0f)
#define KB1 (1.5f)
#define KB2 (-3.0f)
#define KB3 (11.0f/6.0f)

#define IT 8
#define A_INT_Y 254   // amper interior: i0 = 5 + 8*y, i in [5,2036]
#define A_BND_Y 27    // 17 row strips + 10 col strips
#define F_INT_Y 255   // faraday interior: i0 = 2 + 8*y, i in [2,2041]
#define F_BND_Y 13    // 8 row strips + 5 col strips

__device__ __forceinline__ void load_M(float beta, float delta, float gamma,
                                       float& a0, float& a1,
                                       float& m01, float& m11, float& m21) {
    a0  = -0.25f * beta + 0.1f * gamma;
    a1  =  0.25f * beta - 0.1f * gamma;
    m01 =  0.25f * beta + delta - 0.5f - 0.1f * gamma;
    m11 = -2.0f * delta;
    m21 = -0.25f * beta + delta + 0.5f + 0.1f * gamma;
}

// ===========================================================================
// Scalar point functions (verified) — boundary strips.
// ===========================================================================
__device__ void amper_point(int i, int j,
                            const float* __restrict__ Eb,
                            const float* __restrict__ Hxb,
                            const float* __restrict__ Hyb,
                            float a0, float a1, float m01, float m11, float m21,
                            float* __restrict__ Eob) {
    const bool ic = (i >= 2 && i <= NE - 3);
    const bool jc = (j >= 2 && j <= NE - 3);
    float s1 = 0.0f, s2 = 0.0f;

    if (ic && jc) {
        const float* r0 = Hyb + (size_t)(i - 2) * NW + (j - 2);
        const float* r1 = r0 + NW;
        const float* r2 = r1 + NW;
        const float* r3 = r2 + NW;
        s1 += a0  * r0[0] + a1  * r0[2]
            + m01 * r1[0] + m11 * r1[1] + m21 * r1[2]
            + a1  * r2[0] + a0  * r2[2]
            + a0  * r3[0] + a1  * r3[2];
        const float* x0 = Hxb + (size_t)(i - 2) * NH + (j - 2);
        const float* x1 = x0 + NH;
        const float* x2 = x1 + NH;
        s2 += a0 * x0[0] + m01 * x0[1] + a1 * x0[2] + a0 * x0[3]
            + m11 * x1[1]
            + a1 * x2[0] + m21 * x2[1] + a0 * x2[2] + a1 * x2[3];
    }
    if (i >= 1 && j <= NE - 6) {
        const float* r = Hyb + (size_t)(i - 1) * NW + j;
        s1 += KF0 * r[0] + KF1 * r[1] + KF2 * r[2] + KF3 * r[3];
    }
    if (i <= NE - 2 && j >= 5) {
        const float* r = Hyb + (size_t)i * NW + (j - 5);
        s1 += KB0 * r[0] + KB1 * r[1] + KB2 * r[2] + KB3 * r[3];
    }
    if (ic && (j == 1 || j == 2)) {
        const float* r = Hyb + (size_t)(i - 1) * NW + (j - 1);
        s1 += -r[0] + 3.0f * r[1] - 3.0f * r[2] + r[3];
    }
    if (ic && (j == NE - 3 || j == NE - 2)) {
        const float* r = Hyb + (size_t)i * NW + (j - 4);
        s1 += r[0] - 3.0f * r[1] + 3.0f * r[2] - r[3];
    }
    if (i <= NE - 6 && j >= 1) {
        const float* x = Hxb + (size_t)i * NH + (j - 1);
        s2 += KF0 * x[0] + KF1 * x[NH] + KF2 * x[2 * NH] + KF3 * x[3 * NH];
    }
    if (i >= 5 && j <= NE - 2) {
        const float* x = Hxb + (size_t)(i - 5) * NH + j;
        s2 += KB0 * x[0] + KB1 * x[NH] + KB2 * x[2 * NH] + KB3 * x[3 * NH];
    }
    if ((i == 1 || i == 2) && jc) {
        const float* x = Hxb + (size_t)(i - 1) * NH + (j - 1);
        s2 += -x[0] + 3.0f * x[NH] - 3.0f * x[2 * NH] + x[3 * NH];
    }
    if ((i == NE - 3 || i == NE - 2) && jc) {
        const float* x = Hxb + (size_t)(i - 4) * NH + j;
        s2 += x[0] - 3.0f * x[NH] + 3.0f * x[2 * NH] - x[3 * NH];
    }
    Eob[(size_t)i * NE + j] = Eb[(size_t)i * NE + j] + CFLf * (s1 - s2);
}

__device__ void faraday_point(int i, int j,
                              const float* __restrict__ Eb,
                              const float* __restrict__ Hxb,
                              const float* __restrict__ Hyb,
                              float a0, float a1, float m01, float m11, float m21,
                              float* __restrict__ Hxob,
                              float* __restrict__ Hyob) {
    if (i < NW && j < NH) {
        float s3 = 0.0f;
        if (j >= 1 && j <= NH - 2) {
            const float* e0 = Eb + (size_t)i * NE + (j - 1);
            const float* e1 = e0 + NE;
            const float* e2 = e1 + NE;
            s3 += a0 * e0[0] + m01 * e0[1] + a1 * e0[2] + a0 * e0[3]
                + m11 * e1[1]
                + a1 * e2[0] + m21 * e2[1] + a0 * e2[2] + a1 * e2[3];
        }
        if (i <= NH - 4) {
            const float* e = Eb + (size_t)(i + 1) * NE + j;
            s3 += -1.5f * e[0] + 2.0f * e[NE] - 0.5f * e[2 * NE];
        }
        if (i >= 2) {
            const float* e = Eb + (size_t)(i - 1) * NE + (j + 1);
            s3 += 0.5f * e[0] - 2.0f * e[NE] + 1.5f * e[2 * NE];
        }
        const size_t off = (size_t)i * NH + j;
        Hxob[off] = Hxb[off] - CFLf * s3;
    }
    if (i < NH && j < NW) {
        float s4 = 0.0f;
        if (i >= 1 && i <= NH - 2) {
            const float* e0 = Eb + (size_t)(i - 1) * NE + j;
            const float* e1 = e0 + NE;
            const float* e2 = e1 + NE;
            const float* e3 = e2 + NE;
            s4 += a0  * e0[0] + a1  * e0[2]
                + m01 * e1[0] + m11 * e1[1] + m21 * e1[2]
                + a1  * e2[0] + a0  * e2[2]
                + a0  * e3[0] + a1  * e3[2];
        }
        if (j <= NH - 4) {
            const float* e = Eb + (size_t)i * NE + (j + 1);
            s4 += -1.5f * e[0] + 2.0f * e[1] - 0.5f * e[2];
        }
        if (j >= 2) {
            const float* e = Eb + (size_t)(i + 1) * NE + (j - 1);
            s4 += 0.5f * e[0] - 2.0f * e[1] + 1.5f * e[2];
        }
        const size_t off = (size_t)i * NW + j;
        Hyob[off] = Hyb[off] + CFLf * s4;
    }
}

// ===========================================================================
// Fused amper: smem-staged interior (IT=8) + boundary strips.
// ===========================================================================
__global__ __launch_bounds__(256)
void amper_kernel(const float* __restrict__ E,
                  const float* __restrict__ Hx,
                  const float* __restrict__ Hy,
                  const float* __restrict__ pb,
                  const float* __restrict__ pd,
                  const float* __restrict__ pg,
                  float* __restrict__ Eo) {
    const int b = blockIdx.z;
    float a0, a1, m01, m11, m21;
    load_M(*pb, *pd, *pg, a0, a1, m01, m11, m21);

    const float* Eb  = E  + (size_t)b * NE * NE;
    const float* Hxb = Hx + (size_t)b * NW * NH;
    const float* Hyb = Hy + (size_t)b * NH * NW;
    float* Eob = Eo + (size_t)b * NE * NE;

    if (blockIdx.y >= A_INT_Y) {
        const int y = blockIdx.y - A_INT_Y;
        if (y < 17) {
            const int i = (y < 5) ? y : 2037 + (y - 5);
            const int j = blockIdx.x * 256 + threadIdx.x;
            if (j >= NE) return;
            amper_point(i, j, Eb, Hxb, Hyb, a0, a1, m01, m11, m21, Eob);
        } else {
            const int c = y - 17;
            const int j = (c < 5) ? c : 2044 + (c - 5);
            const int i = 5 + blockIdx.x * 256 + threadIdx.x;
            if (i > 2036) return;
            amper_point(i, j, Eb, Hxb, Hyb, a0, a1, m01, m11, m21, Eob);
        }
        return;
    }

    // ---- interior: i0 = 5 + 8*y; block covers j in [jb, jb+255] ∩ [5,2043] ----
    const int jb = 5 + blockIdx.x * 256;
    if (jb > 2043) return;                 // uniform per block (bx == 8)
    const int i0 = 5 + blockIdx.y * IT;
    const int tid = threadIdx.x;

    __shared__ float sHy[IT + 3][264];     // rows i0-2..i0+8, cols jb-5..jb+258
    __shared__ float sHx[IT + 8][260];     // rows i0-5..i0+10, cols jb-2..jb+257

    for (int idx = tid; idx < (IT + 3) * 264; idx += 256) {
        const int r = idx / 264, c = idx - r * 264;
        int gc = jb - 5 + c; if (gc > NW - 1) gc = NW - 1;
        sHy[r][c] = Hyb[(size_t)(i0 - 2 + r) * NW + gc];
    }
    for (int idx = tid; idx < (IT + 8) * 260; idx += 256) {
        const int r = idx / 260, c = idx - r * 260;
        int gc = jb - 2 + c; if (gc > NH - 1) gc = NH - 1;
        sHx[r][c] = Hxb[(size_t)(i0 - 5 + r) * NH + gc];
    }
    __syncthreads();

    const int j = jb + tid;
    const float a1k  = a1 + KB3;
    const float m21k = m21 + KF0;

    float acc[IT];
#pragma unroll
    for (int k = 0; k < IT; k++) acc[k] = 0.0f;

    // ---- s1 from sHy: window cols tid+0 .. tid+8 (= j-5 .. j+3) ----
#pragma unroll
    for (int rr = 0; rr < IT + 3; ++rr) {
        const bool uA = (rr <= IT - 1);
        const bool uB = (rr >= 1 && rr <= IT);
        const bool uC = (rr >= 2 && rr <= IT + 1);
        const bool uD = (rr >= 3);
        const float c0 = sHy[rr][tid + 0];
        const float c1 = sHy[rr][tid + 1];
        const float c2 = sHy[rr][tid + 2];
        const float c3 = sHy[rr][tid + 3];
        const float c4 = sHy[rr][tid + 4];
        const float c5 = sHy[rr][tid + 5];
        const float c6 = sHy[rr][tid + 6];
        const float c7 = sHy[rr][tid + 7];
        const float c8 = sHy[rr][tid + 8];
        const float t = a0 * c3 + a1 * c5;
        if (uA) acc[rr]     += t;
        if (uB) acc[rr - 1] += m01 * c3 + m11 * c4 + m21k * c5
                             + KF1 * c6 + KF2 * c7 + KF3 * c8;
        if (uC) acc[rr - 2] += KB0 * c0 + KB1 * c1 + KB2 * c2
                             + a1k * c3 + a0 * c5;
        if (uD) acc[rr - 3] += t;
    }

    // ---- s2 (subtract) from sHx: window cols tid+0 .. tid+3 (= j-2 .. j+1) ----
#pragma unroll
    for (int rr = 0; rr < IT + 8; ++rr) {
        const bool vK0 = (rr <= IT - 1);
        const bool vK1 = (rr >= 1 && rr <= IT);
        const bool vK2 = (rr >= 2 && rr <= IT + 1);
        const bool vA  = (rr >= 3 && rr <= IT + 2);
        const bool vB  = (rr >= 4 && rr <= IT + 3);
        const bool vC  = (rr >= 5 && rr <= IT + 4);
        const bool vD  = (rr >= 6 && rr <= IT + 5);
        const bool vE  = (rr >= 7 && rr <= IT + 6);
        const bool vF  = (rr >= 8);
        const float d0 = sHx[rr][tid + 0];
        const float d1 = sHx[rr][tid + 1];
        const float d2 = sHx[rr][tid + 2];
        const float d3 = sHx[rr][tid + 3];
        if (vK0) acc[rr]     -= KB0 * d2;
        if (vK1) acc[rr - 1] -= KB1 * d2;
        if (vK2) acc[rr - 2] -= KB2 * d2;
        if (vA)  acc[rr - 3] -= a0 * d0 + m01 * d1 + a1k * d2 + a0 * d3;
        if (vB)  acc[rr - 4] -= m11 * d1;
        if (vC)  acc[rr - 5] -= a1 * d0 + m21k * d1 + a0 * d2 + a1 * d3;
        if (vD)  acc[rr - 6] -= KF1 * d1;
        if (vE)  acc[rr - 7] -= KF2 * d1;
        if (vF)  acc[rr - 8] -= KF3 * d1;
    }

    if (j <= 2043) {
        const size_t off = (size_t)i0 * NE + j;
#pragma unroll
        for (int k = 0; k < IT; k++)
            Eob[off + (size_t)k * NE] = Eb[off + (size_t)k * NE] + CFLf * acc[k];
    }
}

// ===========================================================================
// Fused faraday (Hx+Hy): smem-staged interior (IT=8) + boundary strips.
// ===========================================================================
__global__ __launch_bounds__(256)
void faraday_kernel(const float* __restrict__ E,
                    const float* __restrict__ Hx,
                    const float* __restrict__ Hy,
                    const float* __restrict__ pb,
                    const float* __restrict__ pd,
                    const float* __restrict__ pg,
                    float* __restrict__ Hxo,
                    float* __restrict__ Hyo) {
    const int b = blockIdx.z;
    float a0, a1, m01, m11, m21;
    load_M(*pb, *pd, *pg, a0, a1, m01, m11, m21);

    const float* Eb  = E  + (size_t)b * NE * NE;
    const float* Hxb = Hx + (size_t)b * NW * NH;
    const float* Hyb = Hy + (size_t)b * NH * NW;
    float* Hxob = Hxo + (size_t)b * NW * NH;
    float* Hyob = Hyo + (size_t)b * NH * NW;

    if (blockIdx.y >= F_INT_Y) {
        const int y = blockIdx.y - F_INT_Y;
        if (y < 8) {
            const int i = (y < 2) ? y : 2042 + (y - 2);
            const int j = blockIdx.x * 256 + threadIdx.x;
            if (j >= NH) return;
            faraday_point(i, j, Eb, Hxb, Hyb, a0, a1, m01, m11, m21, Hxob, Hyob);
        } else {
            const int c = y - 8;
            const int j = (c < 2) ? c : 2045 + (c - 2);
            const int i = 2 + blockIdx.x * 256 + threadIdx.x;
            if (i > 2041) return;
            faraday_point(i, j, Eb, Hxb, Hyb, a0, a1, m01, m11, m21, Hxob, Hyob);
        }
        return;
    }

    // ---- interior: i0 = 2 + 8*y; block covers j in [jb, jb+255] ∩ [2,2044] ----
    const int jb = 2 + blockIdx.x * 256;
    const int i0 = 2 + blockIdx.y * IT;
    const int tid = threadIdx.x;

    __shared__ float sE[IT + 4][260];      // rows i0-1..i0+10, cols jb-1..jb+258

    for (int idx = tid; idx < (IT + 4) * 260; idx += 256) {
        const int r = idx / 260, c = idx - r * 260;
        int gc = jb - 1 + c; if (gc > NE - 1) gc = NE - 1;
        sE[r][c] = Eb[(size_t)(i0 - 1 + r) * NE + gc];
    }
    __syncthreads();

    const int j = jb + tid;
    const float m11b = m11 - 1.5f;
    const float m21b = m21 + 2.0f;
    const float a1m2 = a1 - 2.0f;

    float sx[IT], sy[IT];
#pragma unroll
    for (int k = 0; k < IT; k++) { sx[k] = 0.0f; sy[k] = 0.0f; }

#pragma unroll
    for (int rr = 0; rr < IT + 4; ++rr) {
        const bool w0 = (rr <= IT - 1);
        const bool w1 = (rr >= 1 && rr <= IT);
        const bool w2 = (rr >= 2 && rr <= IT + 1);
        const bool w3 = (rr >= 3 && rr <= IT + 2);
        const bool w4 = (rr >= 4);
        const float e0 = sE[rr][tid + 0];
        const float e1 = sE[rr][tid + 1];
        const float e2 = sE[rr][tid + 2];
        const float e3 = sE[rr][tid + 3];
        const float e4 = sE[rr][tid + 4];

        const float ty = a0 * e1 + a1 * e3;
        if (w0) { sx[rr] += 0.5f * e2; sy[rr] += ty; }
        if (w1) {
            sx[rr - 1] += a0 * e0 + m01 * e1 + a1m2 * e2 + a0 * e3;
            sy[rr - 1] += m01 * e1 + m11b * e2 + m21b * e3 - 0.5f * e4;
        }
        if (w2) {
            sx[rr - 2] += m11b * e1 + 1.5f * e2;
            sy[rr - 2] += 0.5f * e0 + a1m2 * e1 + 1.5f * e2 + a0 * e3;
        }
        if (w3) {
            sx[rr - 3] += a1 * e0 + m21b * e1 + a0 * e2 + a1 * e3;
            sy[rr - 3] += ty;
        }
        if (w4) sx[rr - 4] -= 0.5f * e1;
    }

    if (j <= 2044) {
        const size_t offx = (size_t)i0 * NH + j;
        const size_t offy = (size_t)i0 * NW + j;
#pragma unroll
        for (int k = 0; k < IT; k++) {
            Hxob[offx + (size_t)k * NH] = Hxb[offx + (size_t)k * NH] - CFLf * sx[k];
            Hyob[offy + (size_t)k * NW] = Hyb[offy + (size_t)k * NW] + CFLf * sy[k];
        }
    }
}

// ===========================================================================
extern "C" void kernel_launch(void* const* d_in, const int* in_sizes, int n_in,
                              void* d_out, int out_size) {
    const float* E0  = (const float*)d_in[0];
    const float* Hx0 = (const float*)d_in[1];
    const float* Hy0 = (const float*)d_in[2];
    const float* pb  = (const float*)d_in[3];
    const float* pd  = (const float*)d_in[4];
    const float* pg  = (const float*)d_in[5];

    const int B = in_sizes[0] / (NE * NE);

    const size_t nE  = (size_t)B * NE * NE;
    const size_t nHx = (size_t)B * NW * NH;
    const size_t nHy = (size_t)B * NH * NW;

    float* out = (float*)d_out;
    float* E2  = out;
    float* Hx2 = E2 + nE;
    float* Hy2 = Hx2 + nHx;
    float* E3  = Hy2 + nHy;
    float* Hx3 = E3 + nE;
    float* Hy3 = Hx3 + nHx;
    float* E4  = Hy3 + nHy;
    float* Hx4 = E4 + nE;
    float* Hy4 = Hx4 + nHx;

    dim3 blk(256);
    dim3 gA(9, A_INT_Y + A_BND_Y, B);  // x=9 for 2049-wide boundary rows
    dim3 gF(8, F_INT_Y + F_BND_Y, B);

    const float* Ein  = E0;
    const float* Hxin = Hx0;
    const float* Hyin = Hy0;
    float* Eouts[3]  = {E2, E3, E4};
    float* Hxouts[3] = {Hx2, Hx3, Hx4};
    float* Hyouts[3] = {Hy2, Hy3, Hy4};

    for (int s = 0; s < 3; s++) {
        amper_kernel<<<gA, blk>>>(Ein, Hxin, Hyin, pb, pd, pg, Eouts[s]);
        faraday_kernel<<<gF, blk>>>(Eouts[s], Hxin, Hyin, pb, pd, pg,
                                    Hxouts[s], Hyouts[s]);
        Ein = Eouts[s]; Hxin = Hxouts[s]; Hyin = Hyouts[s];
    }
}

// round 8
// speedup vs baseline: 1.3295x; 1.3295x over previous
#include <cuda_runtime.h>

#define NE 2049   // E is NE x NE
#define NH 2048   // Hx cols / Hy rows
#define NW 2047   // Hx rows / Hy cols
#define CFLf 0.35f

#define KF0 (-11.0f/6.0f)
#define KF1 (3.0f)
#define KF2 (-1.5f)
#define KF3 (1.0f/3.0f)
#define KB0 (-1.0f/3.0f)
#define KB1 (1.5f)
#define KB2 (-3.0f)
#define KB3 (11.0f/6.0f)

#define IT 8
#define A_INT_Y 254   // amper interior: i0 = 5 + 8*y, i in [5,2036]
#define A_BND_Y 27    // 17 row strips + 10 col strips
#define F_INT_Y 255   // faraday interior: i0 = 2 + 8*y, i in [2,2041]
#define F_BND_Y 13    // 8 row strips + 5 col strips

__device__ __forceinline__ void load_M(float beta, float delta, float gamma,
                                       float& a0, float& a1,
                                       float& m01, float& m11, float& m21) {
    a0  = -0.25f * beta + 0.1f * gamma;
    a1  =  0.25f * beta - 0.1f * gamma;
    m01 =  0.25f * beta + delta - 0.5f - 0.1f * gamma;
    m11 = -2.0f * delta;
    m21 = -0.25f * beta + delta + 0.5f + 0.1f * gamma;
}

// ===========================================================================
// Scalar point functions (verified) — boundary strips.
// ===========================================================================
__device__ void amper_point(int i, int j,
                            const float* __restrict__ Eb,
                            const float* __restrict__ Hxb,
                            const float* __restrict__ Hyb,
                            float a0, float a1, float m01, float m11, float m21,
                            float* __restrict__ Eob) {
    const bool ic = (i >= 2 && i <= NE - 3);
    const bool jc = (j >= 2 && j <= NE - 3);
    float s1 = 0.0f, s2 = 0.0f;

    if (ic && jc) {
        const float* r0 = Hyb + (size_t)(i - 2) * NW + (j - 2);
        const float* r1 = r0 + NW;
        const float* r2 = r1 + NW;
        const float* r3 = r2 + NW;
        s1 += a0  * r0[0] + a1  * r0[2]
            + m01 * r1[0] + m11 * r1[1] + m21 * r1[2]
            + a1  * r2[0] + a0  * r2[2]
            + a0  * r3[0] + a1  * r3[2];
        const float* x0 = Hxb + (size_t)(i - 2) * NH + (j - 2);
        const float* x1 = x0 + NH;
        const float* x2 = x1 + NH;
        s2 += a0 * x0[0] + m01 * x0[1] + a1 * x0[2] + a0 * x0[3]
            + m11 * x1[1]
            + a1 * x2[0] + m21 * x2[1] + a0 * x2[2] + a1 * x2[3];
    }
    if (i >= 1 && j <= NE - 6) {
        const float* r = Hyb + (size_t)(i - 1) * NW + j;
        s1 += KF0 * r[0] + KF1 * r[1] + KF2 * r[2] + KF3 * r[3];
    }
    if (i <= NE - 2 && j >= 5) {
        const float* r = Hyb + (size_t)i * NW + (j - 5);
        s1 += KB0 * r[0] + KB1 * r[1] + KB2 * r[2] + KB3 * r[3];
    }
    if (ic && (j == 1 || j == 2)) {
        const float* r = Hyb + (size_t)(i - 1) * NW + (j - 1);
        s1 += -r[0] + 3.0f * r[1] - 3.0f * r[2] + r[3];
    }
    if (ic && (j == NE - 3 || j == NE - 2)) {
        const float* r = Hyb + (size_t)i * NW + (j - 4);
        s1 += r[0] - 3.0f * r[1] + 3.0f * r[2] - r[3];
    }
    if (i <= NE - 6 && j >= 1) {
        const float* x = Hxb + (size_t)i * NH + (j - 1);
        s2 += KF0 * x[0] + KF1 * x[NH] + KF2 * x[2 * NH] + KF3 * x[3 * NH];
    }
    if (i >= 5 && j <= NE - 2) {
        const float* x = Hxb + (size_t)(i - 5) * NH + j;
        s2 += KB0 * x[0] + KB1 * x[NH] + KB2 * x[2 * NH] + KB3 * x[3 * NH];
    }
    if ((i == 1 || i == 2) && jc) {
        const float* x = Hxb + (size_t)(i - 1) * NH + (j - 1);
        s2 += -x[0] + 3.0f * x[NH] - 3.0f * x[2 * NH] + x[3 * NH];
    }
    if ((i == NE - 3 || i == NE - 2) && jc) {
        const float* x = Hxb + (size_t)(i - 4) * NH + j;
        s2 += x[0] - 3.0f * x[NH] + 3.0f * x[2 * NH] - x[3 * NH];
    }
    Eob[(size_t)i * NE + j] = Eb[(size_t)i * NE + j] + CFLf * (s1 - s2);
}

__device__ void faraday_point(int i, int j,
                              const float* __restrict__ Eb,
                              const float* __restrict__ Hxb,
                              const float* __restrict__ Hyb,
                              float a0, float a1, float m01, float m11, float m21,
                              float* __restrict__ Hxob,
                              float* __restrict__ Hyob) {
    if (i < NW && j < NH) {
        float s3 = 0.0f;
        if (j >= 1 && j <= NH - 2) {
            const float* e0 = Eb + (size_t)i * NE + (j - 1);
            const float* e1 = e0 + NE;
            const float* e2 = e1 + NE;
            s3 += a0 * e0[0] + m01 * e0[1] + a1 * e0[2] + a0 * e0[3]
                + m11 * e1[1]
                + a1 * e2[0] + m21 * e2[1] + a0 * e2[2] + a1 * e2[3];
        }
        if (i <= NH - 4) {
            const float* e = Eb + (size_t)(i + 1) * NE + j;
            s3 += -1.5f * e[0] + 2.0f * e[NE] - 0.5f * e[2 * NE];
        }
        if (i >= 2) {
            const float* e = Eb + (size_t)(i - 1) * NE + (j + 1);
            s3 += 0.5f * e[0] - 2.0f * e[NE] + 1.5f * e[2 * NE];
        }
        const size_t off = (size_t)i * NH + j;
        Hxob[off] = Hxb[off] - CFLf * s3;
    }
    if (i < NH && j < NW) {
        float s4 = 0.0f;
        if (i >= 1 && i <= NH - 2) {
            const float* e0 = Eb + (size_t)(i - 1) * NE + j;
            const float* e1 = e0 + NE;
            const float* e2 = e1 + NE;
            const float* e3 = e2 + NE;
            s4 += a0  * e0[0] + a1  * e0[2]
                + m01 * e1[0] + m11 * e1[1] + m21 * e1[2]
                + a1  * e2[0] + a0  * e2[2]
                + a0  * e3[0] + a1  * e3[2];
        }
        if (j <= NH - 4) {
            const float* e = Eb + (size_t)i * NE + (j + 1);
            s4 += -1.5f * e[0] + 2.0f * e[1] - 0.5f * e[2];
        }
        if (j >= 2) {
            const float* e = Eb + (size_t)(i + 1) * NE + (j - 1);
            s4 += 0.5f * e[0] - 2.0f * e[1] + 1.5f * e[2];
        }
        const size_t off = (size_t)i * NW + j;
        Hyob[off] = Hyb[off] + CFLf * s4;
    }
}

// ===========================================================================
// Fused amper: interior (IT=8, software-pipelined rows) + boundary strips.
// ===========================================================================
__global__ __launch_bounds__(256, 2)
void amper_kernel(const float* __restrict__ E,
                  const float* __restrict__ Hx,
                  const float* __restrict__ Hy,
                  const float* __restrict__ pb,
                  const float* __restrict__ pd,
                  const float* __restrict__ pg,
                  float* __restrict__ Eo) {
    const int b = blockIdx.z;
    float a0, a1, m01, m11, m21;
    load_M(*pb, *pd, *pg, a0, a1, m01, m11, m21);

    const float* Eb  = E  + (size_t)b * NE * NE;
    const float* Hxb = Hx + (size_t)b * NW * NH;
    const float* Hyb = Hy + (size_t)b * NH * NW;
    float* Eob = Eo + (size_t)b * NE * NE;

    if (blockIdx.y >= A_INT_Y) {
        const int y = blockIdx.y - A_INT_Y;
        if (y < 17) {
            const int i = (y < 5) ? y : 2037 + (y - 5);
            const int j = blockIdx.x * 256 + threadIdx.x;
            if (j >= NE) return;
            amper_point(i, j, Eb, Hxb, Hyb, a0, a1, m01, m11, m21, Eob);
        } else {
            const int c = y - 17;
            const int j = (c < 5) ? c : 2044 + (c - 5);
            const int i = 5 + blockIdx.x * 256 + threadIdx.x;
            if (i > 2036) return;
            amper_point(i, j, Eb, Hxb, Hyb, a0, a1, m01, m11, m21, Eob);
        }
        return;
    }

    // ---- interior: i0 = 5 + 8*y, j in [5, 2043] ----
    const int j = 5 + blockIdx.x * 256 + threadIdx.x;
    if (j > 2043) return;
    const int i0 = 5 + blockIdx.y * IT;

    const float a1k  = a1 + KB3;
    const float m21k = m21 + KF0;

    float acc[IT];
#pragma unroll
    for (int k = 0; k < IT; k++) acc[k] = 0.0f;

    // ---- s1: Hy rows i0-2 .. i0+8, window cols j-5 .. j+3 (pipelined) ----
    {
        const float* hy = Hyb + (size_t)(i0 - 2) * NW + (j - 5);
        float cur[9];
#pragma unroll
        for (int t = 0; t < 9; t++) cur[t] = hy[t];
        hy += NW;
#pragma unroll
        for (int rr = 0; rr < IT + 3; ++rr) {
            float nxt[9];
            if (rr < IT + 2) {
#pragma unroll
                for (int t = 0; t < 9; t++) nxt[t] = hy[t];
                hy += NW;
            }
            const bool uA = (rr <= IT - 1);
            const bool uB = (rr >= 1 && rr <= IT);
            const bool uC = (rr >= 2 && rr <= IT + 1);
            const bool uD = (rr >= 3);
            const float t = a0 * cur[5] + a1 * cur[7];
            if (uA) acc[rr]     += t;
            if (uB) acc[rr - 1] += m01 * cur[5] + m11 * cur[6] + m21k * cur[7]
                                 + KF1 * cur[8] + KF2 * cur[2] * 0.0f  // placeholder never taken
                                 + 0.0f;
            // NOTE: replaced below — see corrected block
            if (uB) acc[rr - 1] += KF2 * 0.0f;
            if (uC) acc[rr - 2] += 0.0f;
            if (uD) acc[rr - 3] += t;
            (void)uC;
#pragma unroll
            for (int tt = 0; tt < 9; tt++) cur[tt] = nxt[tt];
        }
    }

    // The block above is replaced by the correct pipelined loop:
    // (recompute acc from scratch to keep logic exact)
#pragma unroll
    for (int k = 0; k < IT; k++) acc[k] = 0.0f;
    {
        const float* hy = Hyb + (size_t)(i0 - 2) * NW + (j - 5);
        float cur[9];
#pragma unroll
        for (int t = 0; t < 9; t++) cur[t] = hy[t];
        hy += NW;
#pragma unroll
        for (int rr = 0; rr < IT + 3; ++rr) {
            float nxt[9];
            if (rr < IT + 2) {
#pragma unroll
                for (int t = 0; t < 9; t++) nxt[t] = hy[t];
                hy += NW;
            } else {
#pragma unroll
                for (int t = 0; t < 9; t++) nxt[t] = 0.0f;
            }
            const bool uA = (rr <= IT - 1);
            const bool uB = (rr >= 1 && rr <= IT);
            const bool uC = (rr >= 2 && rr <= IT + 1);
            const bool uD = (rr >= 3);
            const float t = a0 * cur[3] + a1 * cur[5];
            if (uA) acc[rr]     += t;
            if (uB) acc[rr - 1] += m01 * cur[3] + m11 * cur[4] + m21k * cur[5]
                                 + KF1 * cur[6] + KF2 * cur[7] + KF3 * cur[8];
            if (uC) acc[rr - 2] += KB0 * cur[0] + KB1 * cur[1] + KB2 * cur[2]
                                 + a1k * cur[3] + a0 * cur[5];
            if (uD) acc[rr - 3] += t;
#pragma unroll
            for (int tt = 0; tt < 9; tt++) cur[tt] = nxt[tt];
        }
    }

    // ---- s2 (subtract): Hx rows i0-5 .. i0+10, window cols j-2 .. j+1 ----
    {
        const float* hx = Hxb + (size_t)(i0 - 5) * NH + (j - 2);
        float cur[4];
#pragma unroll
        for (int t = 0; t < 4; t++) cur[t] = hx[t];
        hx += NH;
#pragma unroll
        for (int rr = 0; rr < IT + 8; ++rr) {
            float nxt[4];
            if (rr < IT + 7) {
#pragma unroll
                for (int t = 0; t < 4; t++) nxt[t] = hx[t];
                hx += NH;
            } else {
#pragma unroll
                for (int t = 0; t < 4; t++) nxt[t] = 0.0f;
            }
            const bool vK0 = (rr <= IT - 1);
            const bool vK1 = (rr >= 1 && rr <= IT);
            const bool vK2 = (rr >= 2 && rr <= IT + 1);
            const bool vA  = (rr >= 3 && rr <= IT + 2);
            const bool vB  = (rr >= 4 && rr <= IT + 3);
            const bool vC  = (rr >= 5 && rr <= IT + 4);
            const bool vD  = (rr >= 6 && rr <= IT + 5);
            const bool vE  = (rr >= 7 && rr <= IT + 6);
            const bool vF  = (rr >= 8);
            if (vK0) acc[rr]     -= KB0 * cur[2];
            if (vK1) acc[rr - 1] -= KB1 * cur[2];
            if (vK2) acc[rr - 2] -= KB2 * cur[2];
            if (vA)  acc[rr - 3] -= a0 * cur[0] + m01 * cur[1] + a1k * cur[2] + a0 * cur[3];
            if (vB)  acc[rr - 4] -= m11 * cur[1];
            if (vC)  acc[rr - 5] -= a1 * cur[0] + m21k * cur[1] + a0 * cur[2] + a1 * cur[3];
            if (vD)  acc[rr - 6] -= KF1 * cur[1];
            if (vE)  acc[rr - 7] -= KF2 * cur[1];
            if (vF)  acc[rr - 8] -= KF3 * cur[1];
#pragma unroll
            for (int tt = 0; tt < 4; tt++) cur[tt] = nxt[tt];
        }
    }

    const size_t off = (size_t)i0 * NE + j;
#pragma unroll
    for (int k = 0; k < IT; k++)
        Eob[off + (size_t)k * NE] = Eb[off + (size_t)k * NE] + CFLf * acc[k];
}

// ===========================================================================
// Fused faraday (Hx+Hy): interior (IT=8, pipelined) + boundary strips.
// ===========================================================================
__global__ __launch_bounds__(256, 2)
void faraday_kernel(const float* __restrict__ E,
                    const float* __restrict__ Hx,
                    const float* __restrict__ Hy,
                    const float* __restrict__ pb,
                    const float* __restrict__ pd,
                    const float* __restrict__ pg,
                    float* __restrict__ Hxo,
                    float* __restrict__ Hyo) {
    const int b = blockIdx.z;
    float a0, a1, m01, m11, m21;
    load_M(*pb, *pd, *pg, a0, a1, m01, m11, m21);

    const float* Eb  = E  + (size_t)b * NE * NE;
    const float* Hxb = Hx + (size_t)b * NW * NH;
    const float* Hyb = Hy + (size_t)b * NH * NW;
    float* Hxob = Hxo + (size_t)b * NW * NH;
    float* Hyob = Hyo + (size_t)b * NH * NW;

    if (blockIdx.y >= F_INT_Y) {
        const int y = blockIdx.y - F_INT_Y;
        if (y < 8) {
            const int i = (y < 2) ? y : 2042 + (y - 2);
            const int j = blockIdx.x * 256 + threadIdx.x;
            if (j >= NH) return;
            faraday_point(i, j, Eb, Hxb, Hyb, a0, a1, m01, m11, m21, Hxob, Hyob);
        } else {
            const int c = y - 8;
            const int j = (c < 2) ? c : 2045 + (c - 2);
            const int i = 2 + blockIdx.x * 256 + threadIdx.x;
            if (i > 2041) return;
            faraday_point(i, j, Eb, Hxb, Hyb, a0, a1, m01, m11, m21, Hxob, Hyob);
        }
        return;
    }

    // ---- interior: i0 = 2 + 8*y, j in [2, 2044] ----
    const int j = 2 + blockIdx.x * 256 + threadIdx.x;
    if (j > 2044) return;
    const int i0 = 2 + blockIdx.y * IT;

    const float m11b = m11 - 1.5f;
    const float m21b = m21 + 2.0f;
    const float a1m2 = a1 - 2.0f;

    float sx[IT], sy[IT];
#pragma unroll
    for (int k = 0; k < IT; k++) { sx[k] = 0.0f; sy[k] = 0.0f; }

    {
        const float* ep = Eb + (size_t)(i0 - 1) * NE + (j - 1);
        float cur[5];
#pragma unroll
        for (int t = 0; t < 5; t++) cur[t] = ep[t];
        ep += NE;
#pragma unroll
        for (int rr = 0; rr < IT + 4; ++rr) {
            float nxt[5];
            if (rr < IT + 3) {
#pragma unroll
                for (int t = 0; t < 5; t++) nxt[t] = ep[t];
                ep += NE;
            } else {
#pragma unroll
                for (int t = 0; t < 5; t++) nxt[t] = 0.0f;
            }
            const bool w0 = (rr <= IT - 1);
            const bool w1 = (rr >= 1 && rr <= IT);
            const bool w2 = (rr >= 2 && rr <= IT + 1);
            const bool w3 = (rr >= 3 && rr <= IT + 2);
            const bool w4 = (rr >= 4);
            const float ty = a0 * cur[1] + a1 * cur[3];
            if (w0) { sx[rr] += 0.5f * cur[2]; sy[rr] += ty; }
            if (w1) {
                sx[rr - 1] += a0 * cur[0] + m01 * cur[1] + a1m2 * cur[2] + a0 * cur[3];
                sy[rr - 1] += m01 * cur[1] + m11b * cur[2] + m21b * cur[3] - 0.5f * cur[4];
            }
            if (w2) {
                sx[rr - 2] += m11b * cur[1] + 1.5f * cur[2];
                sy[rr - 2] += 0.5f * cur[0] + a1m2 * cur[1] + 1.5f * cur[2] + a0 * cur[3];
            }
            if (w3) {
                sx[rr - 3] += a1 * cur[0] + m21b * cur[1] + a0 * cur[2] + a1 * cur[3];
                sy[rr - 3] += ty;
            }
            if (w4) sx[rr - 4] -= 0.5f * cur[1];
#pragma unroll
            for (int tt = 0; tt < 5; tt++) cur[tt] = nxt[tt];
        }
    }

    const size_t offx = (size_t)i0 * NH + j;
    const size_t offy = (size_t)i0 * NW + j;
#pragma unroll
    for (int k = 0; k < IT; k++) {
        Hxob[offx + (size_t)k * NH] = Hxb[offx + (size_t)k * NH] - CFLf * sx[k];
        Hyob[offy + (size_t)k * NW] = Hyb[offy + (size_t)k * NW] + CFLf * sy[k];
    }
}

// ===========================================================================
extern "C" void kernel_launch(void* const* d_in, const int* in_sizes, int n_in,
                              void* d_out, int out_size) {
    const float* E0  = (const float*)d_in[0];
    const float* Hx0 = (const float*)d_in[1];
    const float* Hy0 = (const float*)d_in[2];
    const float* pb  = (const float*)d_in[3];
    const float* pd  = (const float*)d_in[4];
    const float* pg  = (const float*)d_in[5];

    const int B = in_sizes[0] / (NE * NE);

    const size_t nE  = (size_t)B * NE * NE;
    const size_t nHx = (size_t)B * NW * NH;
    const size_t nHy = (size_t)B * NH * NW;

    float* out = (float*)d_out;
    float* E2  = out;
    float* Hx2 = E2 + nE;
    float* Hy2 = Hx2 + nHx;
    float* E3  = Hy2 + nHy;
    float* Hx3 = E3 + nE;
    float* Hy3 = Hx3 + nHx;
    float* E4  = Hy3 + nHy;
    float* Hx4 = E4 + nE;
    float* Hy4 = Hx4 + nHx;

    dim3 blk(256);
    dim3 gA(9, A_INT_Y + A_BND_Y, B);  // x=9 for 2049-wide boundary rows
    dim3 gF(8, F_INT_Y + F_BND_Y, B);

    const float* Ein  = E0;
    const float* Hxin = Hx0;
    const float* Hyin = Hy0;
    float* Eouts[3]  = {E2, E3, E4};
    float* Hxouts[3] = {Hx2, Hx3, Hx4};
    float* Hyouts[3] = {Hy2, Hy3, Hy4};

    for (int s = 0; s < 3; s++) {
        amper_kernel<<<gA, blk>>>(Ein, Hxin, Hyin, pb, pd, pg, Eouts[s]);
        faraday_kernel<<<gF, blk>>>(Eouts[s], Hxin, Hyin, pb, pd, pg,
                                    Hxouts[s], Hyouts[s]);
        Ein = Eouts[s]; Hxin = Hxouts[s]; Hyin = Hyouts[s];
    }
}

// round 9
// speedup vs baseline: 1.5558x; 1.1702x over previous
#include <cuda_runtime.h>

#define NE 2049   // E is NE x NE
#define NH 2048   // Hx cols / Hy rows
#define NW 2047   // Hx rows / Hy cols
#define CFLf 0.35f

#define KF0 (-11.0f/6.0f)
#define KF1 (3.0f)
#define KF2 (-1.5f)
#define KF3 (1.0f/3.0f)
#define KB0 (-1.0f/3.0f)
#define KB1 (1.5f)
#define KB2 (-3.0f)
#define KB3 (11.0f/6.0f)

#define AIT 16        // amper i-tile
#define FIT 12        // faraday i-tile
#define A_INT_Y 127   // amper interior: i0 = 5 + 16*y, i in [5,2036] (2032 rows)
#define A_BND_Y 27    // 17 row strips + 10 col strips
#define F_INT_Y 170   // faraday interior: i0 = 2 + 12*y, i in [2,2041] (2040 rows)
#define F_BND_Y 13    // 8 row strips + 5 col strips

__device__ __forceinline__ void load_M(float beta, float delta, float gamma,
                                       float& a0, float& a1,
                                       float& m01, float& m11, float& m21) {
    a0  = -0.25f * beta + 0.1f * gamma;
    a1  =  0.25f * beta - 0.1f * gamma;
    m01 =  0.25f * beta + delta - 0.5f - 0.1f * gamma;
    m11 = -2.0f * delta;
    m21 = -0.25f * beta + delta + 0.5f + 0.1f * gamma;
}

// ===========================================================================
// Scalar point functions (verified) — boundary strips.
// ===========================================================================
__device__ void amper_point(int i, int j,
                            const float* __restrict__ Eb,
                            const float* __restrict__ Hxb,
                            const float* __restrict__ Hyb,
                            float a0, float a1, float m01, float m11, float m21,
                            float* __restrict__ Eob) {
    const bool ic = (i >= 2 && i <= NE - 3);
    const bool jc = (j >= 2 && j <= NE - 3);
    float s1 = 0.0f, s2 = 0.0f;

    if (ic && jc) {
        const float* r0 = Hyb + (size_t)(i - 2) * NW + (j - 2);
        const float* r1 = r0 + NW;
        const float* r2 = r1 + NW;
        const float* r3 = r2 + NW;
        s1 += a0  * r0[0] + a1  * r0[2]
            + m01 * r1[0] + m11 * r1[1] + m21 * r1[2]
            + a1  * r2[0] + a0  * r2[2]
            + a0  * r3[0] + a1  * r3[2];
        const float* x0 = Hxb + (size_t)(i - 2) * NH + (j - 2);
        const float* x1 = x0 + NH;
        const float* x2 = x1 + NH;
        s2 += a0 * x0[0] + m01 * x0[1] + a1 * x0[2] + a0 * x0[3]
            + m11 * x1[1]
            + a1 * x2[0] + m21 * x2[1] + a0 * x2[2] + a1 * x2[3];
    }
    if (i >= 1 && j <= NE - 6) {
        const float* r = Hyb + (size_t)(i - 1) * NW + j;
        s1 += KF0 * r[0] + KF1 * r[1] + KF2 * r[2] + KF3 * r[3];
    }
    if (i <= NE - 2 && j >= 5) {
        const float* r = Hyb + (size_t)i * NW + (j - 5);
        s1 += KB0 * r[0] + KB1 * r[1] + KB2 * r[2] + KB3 * r[3];
    }
    if (ic && (j == 1 || j == 2)) {
        const float* r = Hyb + (size_t)(i - 1) * NW + (j - 1);
        s1 += -r[0] + 3.0f * r[1] - 3.0f * r[2] + r[3];
    }
    if (ic && (j == NE - 3 || j == NE - 2)) {
        const float* r = Hyb + (size_t)i * NW + (j - 4);
        s1 += r[0] - 3.0f * r[1] + 3.0f * r[2] - r[3];
    }
    if (i <= NE - 6 && j >= 1) {
        const float* x = Hxb + (size_t)i * NH + (j - 1);
        s2 += KF0 * x[0] + KF1 * x[NH] + KF2 * x[2 * NH] + KF3 * x[3 * NH];
    }
    if (i >= 5 && j <= NE - 2) {
        const float* x = Hxb + (size_t)(i - 5) * NH + j;
        s2 += KB0 * x[0] + KB1 * x[NH] + KB2 * x[2 * NH] + KB3 * x[3 * NH];
    }
    if ((i == 1 || i == 2) && jc) {
        const float* x = Hxb + (size_t)(i - 1) * NH + (j - 1);
        s2 += -x[0] + 3.0f * x[NH] - 3.0f * x[2 * NH] + x[3 * NH];
    }
    if ((i == NE - 3 || i == NE - 2) && jc) {
        const float* x = Hxb + (size_t)(i - 4) * NH + j;
        s2 += x[0] - 3.0f * x[NH] + 3.0f * x[2 * NH] - x[3 * NH];
    }
    Eob[(size_t)i * NE + j] = Eb[(size_t)i * NE + j] + CFLf * (s1 - s2);
}

__device__ void faraday_point(int i, int j,
                              const float* __restrict__ Eb,
                              const float* __restrict__ Hxb,
                              const float* __restrict__ Hyb,
                              float a0, float a1, float m01, float m11, float m21,
                              float* __restrict__ Hxob,
                              float* __restrict__ Hyob) {
    if (i < NW && j < NH) {
        float s3 = 0.0f;
        if (j >= 1 && j <= NH - 2) {
            const float* e0 = Eb + (size_t)i * NE + (j - 1);
            const float* e1 = e0 + NE;
            const float* e2 = e1 + NE;
            s3 += a0 * e0[0] + m01 * e0[1] + a1 * e0[2] + a0 * e0[3]
                + m11 * e1[1]
                + a1 * e2[0] + m21 * e2[1] + a0 * e2[2] + a1 * e2[3];
        }
        if (i <= NH - 4) {
            const float* e = Eb + (size_t)(i + 1) * NE + j;
            s3 += -1.5f * e[0] + 2.0f * e[NE] - 0.5f * e[2 * NE];
        }
        if (i >= 2) {
            const float* e = Eb + (size_t)(i - 1) * NE + (j + 1);
            s3 += 0.5f * e[0] - 2.0f * e[NE] + 1.5f * e[2 * NE];
        }
        const size_t off = (size_t)i * NH + j;
        Hxob[off] = Hxb[off] - CFLf * s3;
    }
    if (i < NH && j < NW) {
        float s4 = 0.0f;
        if (i >= 1 && i <= NH - 2) {
            const float* e0 = Eb + (size_t)(i - 1) * NE + j;
            const float* e1 = e0 + NE;
            const float* e2 = e1 + NE;
            const float* e3 = e2 + NE;
            s4 += a0  * e0[0] + a1  * e0[2]
                + m01 * e1[0] + m11 * e1[1] + m21 * e1[2]
                + a1  * e2[0] + a0  * e2[2]
                + a0  * e3[0] + a1  * e3[2];
        }
        if (j <= NH - 4) {
            const float* e = Eb + (size_t)i * NE + (j + 1);
            s4 += -1.5f * e[0] + 2.0f * e[1] - 0.5f * e[2];
        }
        if (j >= 2) {
            const float* e = Eb + (size_t)(i + 1) * NE + (j - 1);
            s4 += 0.5f * e[0] - 2.0f * e[1] + 1.5f * e[2];
        }
        const size_t off = (size_t)i * NW + j;
        Hyob[off] = Hyb[off] + CFLf * s4;
    }
}

// ===========================================================================
// Fused amper: interior AIT=16 + boundary strips.
// ===========================================================================
__global__ __launch_bounds__(256)
void amper_kernel(const float* __restrict__ E,
                  const float* __restrict__ Hx,
                  const float* __restrict__ Hy,
                  const float* __restrict__ pb,
                  const float* __restrict__ pd,
                  const float* __restrict__ pg,
                  float* __restrict__ Eo) {
    const int b = blockIdx.z;
    float a0, a1, m01, m11, m21;
    load_M(*pb, *pd, *pg, a0, a1, m01, m11, m21);

    const float* Eb  = E  + (size_t)b * NE * NE;
    const float* Hxb = Hx + (size_t)b * NW * NH;
    const float* Hyb = Hy + (size_t)b * NH * NW;
    float* Eob = Eo + (size_t)b * NE * NE;

    if (blockIdx.y >= A_INT_Y) {
        const int y = blockIdx.y - A_INT_Y;
        if (y < 17) {
            const int i = (y < 5) ? y : 2037 + (y - 5);
            const int j = blockIdx.x * 256 + threadIdx.x;
            if (j >= NE) return;
            amper_point(i, j, Eb, Hxb, Hyb, a0, a1, m01, m11, m21, Eob);
        } else {
            const int c = y - 17;
            const int j = (c < 5) ? c : 2044 + (c - 5);
            const int i = 5 + blockIdx.x * 256 + threadIdx.x;
            if (i > 2036) return;
            amper_point(i, j, Eb, Hxb, Hyb, a0, a1, m01, m11, m21, Eob);
        }
        return;
    }

    // ---- interior: i0 = 5 + 16*y, j in [5, 2043] ----
    const int j = 5 + blockIdx.x * 256 + threadIdx.x;
    if (j > 2043) return;
    const int i0 = 5 + blockIdx.y * AIT;

    const float a1k  = a1 + KB3;
    const float m21k = m21 + KF0;

    float acc[AIT];
#pragma unroll
    for (int k = 0; k < AIT; k++) acc[k] = 0.0f;

    // ---- s1: Hy rows i0-2 .. i0+AIT, window cols j-5 .. j+3 ----
    {
        const float* hy = Hyb + (size_t)(i0 - 2) * NW + (j - 5);
#pragma unroll
        for (int rr = 0; rr < AIT + 3; ++rr) {
            const bool uA = (rr <= AIT - 1);
            const bool uB = (rr >= 1 && rr <= AIT);
            const bool uC = (rr >= 2 && rr <= AIT + 1);
            const bool uD = (rr >= 3);
            float c0 = 0.f, c1 = 0.f, c2 = 0.f, c4 = 0.f, c6 = 0.f, c7 = 0.f, c8 = 0.f;
            const float c3 = hy[3];
            const float c5 = hy[5];
            if (uC) { c0 = hy[0]; c1 = hy[1]; c2 = hy[2]; }
            if (uB) { c4 = hy[4]; c6 = hy[6]; c7 = hy[7]; c8 = hy[8]; }
            const float t = a0 * c3 + a1 * c5;
            if (uA) acc[rr]     += t;
            if (uB) acc[rr - 1] += m01 * c3 + m11 * c4 + m21k * c5
                                 + KF1 * c6 + KF2 * c7 + KF3 * c8;
            if (uC) acc[rr - 2] += KB0 * c0 + KB1 * c1 + KB2 * c2
                                 + a1k * c3 + a0 * c5;
            if (uD) acc[rr - 3] += t;
            hy += NW;
        }
    }

    // ---- s2 (subtract): Hx rows i0-5 .. i0+AIT+2, window cols j-2 .. j+1 ----
    {
        const float* hx = Hxb + (size_t)(i0 - 5) * NH + (j - 2);
#pragma unroll
        for (int rr = 0; rr < AIT + 8; ++rr) {
            const bool vK0 = (rr <= AIT - 1);
            const bool vK1 = (rr >= 1 && rr <= AIT);
            const bool vK2 = (rr >= 2 && rr <= AIT + 1);
            const bool vA  = (rr >= 3 && rr <= AIT + 2);
            const bool vB  = (rr >= 4 && rr <= AIT + 3);
            const bool vC  = (rr >= 5 && rr <= AIT + 4);
            const bool vD  = (rr >= 6 && rr <= AIT + 5);
            const bool vE  = (rr >= 7 && rr <= AIT + 6);
            const bool vF  = (rr >= 8);
            float d0 = 0.f, d1 = 0.f, d2 = 0.f, d3 = 0.f;
            if (vA | vC) { d0 = hx[0]; d3 = hx[3]; }
            if (vA | vB | vC | vD | vE | vF) d1 = hx[1];
            if (vK0 | vK1 | vK2 | vA | vC) d2 = hx[2];
            if (vK0) acc[rr]     -= KB0 * d2;
            if (vK1) acc[rr - 1] -= KB1 * d2;
            if (vK2) acc[rr - 2] -= KB2 * d2;
            if (vA)  acc[rr - 3] -= a0 * d0 + m01 * d1 + a1k * d2 + a0 * d3;
            if (vB)  acc[rr - 4] -= m11 * d1;
            if (vC)  acc[rr - 5] -= a1 * d0 + m21k * d1 + a0 * d2 + a1 * d3;
            if (vD)  acc[rr - 6] -= KF1 * d1;
            if (vE)  acc[rr - 7] -= KF2 * d1;
            if (vF)  acc[rr - 8] -= KF3 * d1;
            hx += NH;
        }
    }

    const size_t off = (size_t)i0 * NE + j;
#pragma unroll
    for (int k = 0; k < AIT; k++)
        Eob[off + (size_t)k * NE] = Eb[off + (size_t)k * NE] + CFLf * acc[k];
}

// ===========================================================================
// Fused faraday (Hx+Hy): interior FIT=12 + boundary strips.
// ===========================================================================
__global__ __launch_bounds__(256)
void faraday_kernel(const float* __restrict__ E,
                    const float* __restrict__ Hx,
                    const float* __restrict__ Hy,
                    const float* __restrict__ pb,
                    const float* __restrict__ pd,
                    const float* __restrict__ pg,
                    float* __restrict__ Hxo,
                    float* __restrict__ Hyo) {
    const int b = blockIdx.z;
    float a0, a1, m01, m11, m21;
    load_M(*pb, *pd, *pg, a0, a1, m01, m11, m21);

    const float* Eb  = E  + (size_t)b * NE * NE;
    const float* Hxb = Hx + (size_t)b * NW * NH;
    const float* Hyb = Hy + (size_t)b * NH * NW;
    float* Hxob = Hxo + (size_t)b * NW * NH;
    float* Hyob = Hyo + (size_t)b * NH * NW;

    if (blockIdx.y >= F_INT_Y) {
        const int y = blockIdx.y - F_INT_Y;
        if (y < 8) {
            const int i = (y < 2) ? y : 2042 + (y - 2);
            const int j = blockIdx.x * 256 + threadIdx.x;
            if (j >= NH) return;
            faraday_point(i, j, Eb, Hxb, Hyb, a0, a1, m01, m11, m21, Hxob, Hyob);
        } else {
            const int c = y - 8;
            const int j = (c < 2) ? c : 2045 + (c - 2);
            const int i = 2 + blockIdx.x * 256 + threadIdx.x;
            if (i > 2041) return;
            faraday_point(i, j, Eb, Hxb, Hyb, a0, a1, m01, m11, m21, Hxob, Hyob);
        }
        return;
    }

    // ---- interior: i0 = 2 + 12*y, j in [2, 2044] ----
    const int j = 2 + blockIdx.x * 256 + threadIdx.x;
    if (j > 2044) return;
    const int i0 = 2 + blockIdx.y * FIT;

    const float m11b = m11 - 1.5f;
    const float m21b = m21 + 2.0f;
    const float a1m2 = a1 - 2.0f;

    float sx[FIT], sy[FIT];
#pragma unroll
    for (int k = 0; k < FIT; k++) { sx[k] = 0.0f; sy[k] = 0.0f; }

    const float* ep = Eb + (size_t)(i0 - 1) * NE + (j - 1);
#pragma unroll
    for (int rr = 0; rr < FIT + 4; ++rr) {
        const bool w0 = (rr <= FIT - 1);
        const bool w1 = (rr >= 1 && rr <= FIT);
        const bool w2 = (rr >= 2 && rr <= FIT + 1);
        const bool w3 = (rr >= 3 && rr <= FIT + 2);
        const bool w4 = (rr >= 4);
        float e0 = 0.f, e2 = 0.f, e3 = 0.f, e4 = 0.f;
        const float e1 = ep[1];
        if (w1 | w2 | w3) e0 = ep[0];
        if (w0 | w1 | w2 | w3) { e2 = ep[2]; e3 = ep[3]; }
        if (w1) e4 = ep[4];

        const float ty = a0 * e1 + a1 * e3;
        if (w0) { sx[rr] += 0.5f * e2; sy[rr] += ty; }
        if (w1) {
            sx[rr - 1] += a0 * e0 + m01 * e1 + a1m2 * e2 + a0 * e3;
            sy[rr - 1] += m01 * e1 + m11b * e2 + m21b * e3 - 0.5f * e4;
        }
        if (w2) {
            sx[rr - 2] += m11b * e1 + 1.5f * e2;
            sy[rr - 2] += 0.5f * e0 + a1m2 * e1 + 1.5f * e2 + a0 * e3;
        }
        if (w3) {
            sx[rr - 3] += a1 * e0 + m21b * e1 + a0 * e2 + a1 * e3;
            sy[rr - 3] += ty;
        }
        if (w4) sx[rr - 4] -= 0.5f * e1;
        ep += NE;
    }

    const size_t offx = (size_t)i0 * NH + j;
    const size_t offy = (size_t)i0 * NW + j;
#pragma unroll
    for (int k = 0; k < FIT; k++) {
        Hxob[offx + (size_t)k * NH] = Hxb[offx + (size_t)k * NH] - CFLf * sx[k];
        Hyob[offy + (size_t)k * NW] = Hyb[offy + (size_t)k * NW] + CFLf * sy[k];
    }
}

// ===========================================================================
extern "C" void kernel_launch(void* const* d_in, const int* in_sizes, int n_in,
                              void* d_out, int out_size) {
    const float* E0  = (const float*)d_in[0];
    const float* Hx0 = (const float*)d_in[1];
    const float* Hy0 = (const float*)d_in[2];
    const float* pb  = (const float*)d_in[3];
    const float* pd  = (const float*)d_in[4];
    const float* pg  = (const float*)d_in[5];

    const int B = in_sizes[0] / (NE * NE);

    const size_t nE  = (size_t)B * NE * NE;
    const size_t nHx = (size_t)B * NW * NH;
    const size_t nHy = (size_t)B * NH * NW;

    float* out = (float*)d_out;
    float* E2  = out;
    float* Hx2 = E2 + nE;
    float* Hy2 = Hx2 + nHx;
    float* E3  = Hy2 + nHy;
    float* Hx3 = E3 + nE;
    float* Hy3 = Hx3 + nHx;
    float* E4  = Hy3 + nHy;
    float* Hx4 = E4 + nE;
    float* Hy4 = Hx4 + nHx;

    dim3 blk(256);
    dim3 gA(9, A_INT_Y + A_BND_Y, B);  // x=9 for 2049-wide boundary rows
    dim3 gF(8, F_INT_Y + F_BND_Y, B);

    const float* Ein  = E0;
    const float* Hxin = Hx0;
    const float* Hyin = Hy0;
    float* Eouts[3]  = {E2, E3, E4};
    float* Hxouts[3] = {Hx2, Hx3, Hx4};
    float* Hyouts[3] = {Hy2, Hy3, Hy4};

    for (int s = 0; s < 3; s++) {
        amper_kernel<<<gA, blk>>>(Ein, Hxin, Hyin, pb, pd, pg, Eouts[s]);
        faraday_kernel<<<gF, blk>>>(Eouts[s], Hxin, Hyin, pb, pd, pg,
                                    Hxouts[s], Hyouts[s]);
        Ein = Eouts[s]; Hxin = Hxouts[s]; Hyin = Hyouts[s];
    }
}